// round 2
// baseline (speedup 1.0000x reference)
#include <cuda_runtime.h>
#include <cuda_bf16.h>
#include <cstdint>

// ---------------------------------------------------------------------------
// GCN 2-layer forward, N=50000 nodes, d 128->128->64, E=800000 edges + loops.
// edge_index is int32 (JAX x64-disabled downcasts the int64 request).
// Pipeline (graph-capturable, allocation-free):
//   1. deg init (=1 self loop) + histogram over dst + rsqrt -> g_dinv
//   2. GEMM1: H1 = x @ W1
//   3. OUT1 init = H1[i]*dinv[i]^2 (self-loop term)
//   4. scatter1: OUT1[dst] += H1[src]*dinv[src]*dinv[dst]  (float4 atomics)
//   5. GEMM2: H2 = relu(OUT1 + b1) @ W2   (bias+relu fused in A-prologue)
//   6. OUT  init = b2 + H2[i]*dinv[i]^2
//   7. scatter2: OUT[dst] += H2[src]*norm
// ---------------------------------------------------------------------------

#define N_NODES 50000
#define D_IN    128
#define D_HID   128
#define D_OUT   64

// scratch (device globals: allocation-free)
__device__ float g_dinv[N_NODES];
__device__ float g_H1[(size_t)N_NODES * D_HID];
__device__ float g_OUT1[(size_t)N_NODES * D_HID];
__device__ float g_H2[(size_t)N_NODES * D_OUT];

// ---------------------------------------------------------------------------
// degree / normalization
// ---------------------------------------------------------------------------
__global__ void k_deg_init(int n) {
    int i = blockIdx.x * blockDim.x + threadIdx.x;
    if (i < n) g_dinv[i] = 1.0f;   // self loop
}

__global__ void k_deg_hist(const int* __restrict__ dst, int E) {
    int e = blockIdx.x * blockDim.x + threadIdx.x;
    if (e < E) atomicAdd(&g_dinv[dst[e]], 1.0f);
}

__global__ void k_deg_rsqrt(int n) {
    int i = blockIdx.x * blockDim.x + threadIdx.x;
    if (i < n) g_dinv[i] = rsqrtf(g_dinv[i]);
}

// ---------------------------------------------------------------------------
// GEMM: C[M,N] = op(A)[M,K] @ W[K,N].  op = identity or relu(a + bias[k]).
// 64x64 tile, TK=32, 256 threads, 4x4 per-thread register block.
// ---------------------------------------------------------------------------
template <bool RELU_BIAS>
__global__ void k_gemm(const float* __restrict__ A,
                       const float* __restrict__ bias,
                       const float* __restrict__ W,
                       float* __restrict__ C,
                       int M, int K, int N) {
    __shared__ float As[32][64];  // [k][row]
    __shared__ float Bs[32][64];  // [k][col]

    const int block_row = blockIdx.y * 64;
    const int block_col = blockIdx.x * 64;
    const int tid = threadIdx.x;
    const int ty = tid >> 4;          // 0..15
    const int tx = tid & 15;          // 0..15
    const int row0 = ty * 4;
    const int col0 = tx * 4;

    float acc[4][4] = {};

    for (int k0 = 0; k0 < K; k0 += 32) {
        // load A tile 64x32 (transposed into smem), coalesced in k
        #pragma unroll
        for (int i = 0; i < 8; i++) {
            int lin = tid + i * 256;
            int r = lin >> 5;
            int kk = lin & 31;
            int grow = block_row + r;
            float v = 0.f;
            if (grow < M) {
                v = A[(size_t)grow * K + k0 + kk];
                if (RELU_BIAS) v = fmaxf(v + bias[k0 + kk], 0.f);
            }
            As[kk][r] = v;
        }
        // load B tile 32x64, coalesced in n
        #pragma unroll
        for (int i = 0; i < 8; i++) {
            int lin = tid + i * 256;
            int kr = lin >> 6;
            int c = lin & 63;
            Bs[kr][c] = W[(size_t)(k0 + kr) * N + block_col + c];
        }
        __syncthreads();

        #pragma unroll
        for (int kk = 0; kk < 32; kk++) {
            float4 a4 = *reinterpret_cast<const float4*>(&As[kk][row0]);
            float4 b4 = *reinterpret_cast<const float4*>(&Bs[kk][col0]);
            float a[4] = {a4.x, a4.y, a4.z, a4.w};
            float b[4] = {b4.x, b4.y, b4.z, b4.w};
            #pragma unroll
            for (int i = 0; i < 4; i++)
                #pragma unroll
                for (int j = 0; j < 4; j++)
                    acc[i][j] = fmaf(a[i], b[j], acc[i][j]);
        }
        __syncthreads();
    }

    #pragma unroll
    for (int i = 0; i < 4; i++) {
        int grow = block_row + row0 + i;
        if (grow < M) {
            float4 v = make_float4(acc[i][0], acc[i][1], acc[i][2], acc[i][3]);
            *reinterpret_cast<float4*>(&C[(size_t)grow * N + block_col + col0]) = v;
        }
    }
}

// ---------------------------------------------------------------------------
// output initializers (self-loop contribution, + bias for layer 2)
// ---------------------------------------------------------------------------
__global__ void k_init_out1(int n) {   // OUT1 = H1 * dinv^2
    size_t idx = (size_t)blockIdx.x * blockDim.x + threadIdx.x;
    size_t total = (size_t)n * D_HID;
    if (idx >= total) return;
    int i = (int)(idx >> 7);           // /128
    float dv = g_dinv[i];
    g_OUT1[idx] = g_H1[idx] * dv * dv;
}

__global__ void k_init_out2(const float* __restrict__ b2,
                            float* __restrict__ out, int n) {
    size_t idx = (size_t)blockIdx.x * blockDim.x + threadIdx.x;
    size_t total = (size_t)n * D_OUT;
    if (idx >= total) return;
    int i = (int)(idx >> 6);           // /64
    int j = (int)(idx & 63);
    float dv = g_dinv[i];
    out[idx] = b2[j] + g_H2[idx] * dv * dv;
}

// ---------------------------------------------------------------------------
// edge scatter: one thread per (edge, float4 chunk). D4 = feature dim / 4.
//   out[dst] += H[src] * dinv[src]*dinv[dst]
// float4 atomicAdd is native on sm_90+.
// ---------------------------------------------------------------------------
template <int D4>
__global__ void k_scatter(const float4* __restrict__ H,
                          const int* __restrict__ srcs,
                          const int* __restrict__ dsts,
                          float4* __restrict__ out, int E) {
    long long idx = (long long)blockIdx.x * blockDim.x + threadIdx.x;
    long long e = idx / D4;
    int q = (int)(idx % D4);
    if (e >= E) return;
    int s = __ldg(&srcs[e]);
    int d = __ldg(&dsts[e]);
    float norm = g_dinv[s] * g_dinv[d];
    float4 v = __ldg(&H[(size_t)s * D4 + q]);
    v.x *= norm; v.y *= norm; v.z *= norm; v.w *= norm;
    atomicAdd(&out[(size_t)d * D4 + q], v);
}

// ---------------------------------------------------------------------------
// launch
// ---------------------------------------------------------------------------
extern "C" void kernel_launch(void* const* d_in, const int* in_sizes, int n_in,
                              void* d_out, int out_size) {
    const float* x   = (const float*)d_in[0];
    const int*   ei  = (const int*)d_in[1];    // int32! (JAX x64 disabled)
    const float* W1  = (const float*)d_in[2];
    const float* b1  = (const float*)d_in[3];
    const float* W2  = (const float*)d_in[4];
    const float* b2  = (const float*)d_in[5];
    float*       out = (float*)d_out;

    const int n = in_sizes[0] / D_IN;       // 50000
    const int E = in_sizes[1] / 2;          // 800000
    const int* srcs = ei;
    const int* dsts = ei + E;

    float* H1   = nullptr;
    float* OUT1 = nullptr;
    float* H2   = nullptr;
    cudaGetSymbolAddress((void**)&H1,   g_H1);
    cudaGetSymbolAddress((void**)&OUT1, g_OUT1);
    cudaGetSymbolAddress((void**)&H2,   g_H2);

    const int T = 256;

    // 1. normalization
    k_deg_init<<<(n + T - 1) / T, T>>>(n);
    k_deg_hist<<<(E + T - 1) / T, T>>>(dsts, E);
    k_deg_rsqrt<<<(n + T - 1) / T, T>>>(n);

    // 2. GEMM1: H1 = x @ W1   (M=n, K=128, N=128)
    {
        dim3 grid(D_HID / 64, (n + 63) / 64);
        k_gemm<false><<<grid, 256>>>(x, nullptr, W1, H1, n, D_IN, D_HID);
    }

    // 3. OUT1 init (self loop)
    {
        size_t total = (size_t)n * D_HID;
        k_init_out1<<<(int)((total + T - 1) / T), T>>>(n);
    }

    // 4. scatter layer 1 (32 float4 chunks per edge)
    {
        long long work = (long long)E * (D_HID / 4);
        k_scatter<D_HID / 4><<<(int)((work + T - 1) / T), T>>>(
            (const float4*)H1, srcs, dsts, (float4*)OUT1, E);
    }

    // 5. GEMM2: H2 = relu(OUT1 + b1) @ W2   (M=n, K=128, N=64)
    {
        dim3 grid(D_OUT / 64, (n + 63) / 64);
        k_gemm<true><<<grid, 256>>>(OUT1, b1, W2, H2, n, D_HID, D_OUT);
    }

    // 6. OUT init (self loop + bias)
    {
        size_t total = (size_t)n * D_OUT;
        k_init_out2<<<(int)((total + T - 1) / T), T>>>(b2, out, n);
    }

    // 7. scatter layer 2 (16 float4 chunks per edge)
    {
        long long work = (long long)E * (D_OUT / 4);
        k_scatter<D_OUT / 4><<<(int)((work + T - 1) / T), T>>>(
            (const float4*)H2, srcs, dsts, (float4*)out, E);
    }
}

// round 3
// speedup vs baseline: 1.4003x; 1.4003x over previous
#include <cuda_runtime.h>
#include <cuda_bf16.h>
#include <mma.h>
#include <cstdint>

using namespace nvcuda;

// ---------------------------------------------------------------------------
// GCN 2-layer forward. N=50000, d 128->128->64, E=800000 (+ implicit self loops)
// edge_index is int32. tf32 tensor-core GEMMs, float4-atomic scatter.
// ---------------------------------------------------------------------------

#define N_NODES 50000
#define M_PAD   50048        // 50000 rounded up to 128
#define D_IN    128
#define D_HID   128
#define D_OUT   64

__device__ float g_dinv[N_NODES];
__device__ float g_H1[(size_t)M_PAD * D_HID];
__device__ float g_OUT1[(size_t)M_PAD * D_HID];
__device__ float g_H2[(size_t)M_PAD * D_OUT];

// ---------------------------------------------------------------------------
// degree / normalization
// ---------------------------------------------------------------------------
__global__ void k_deg_init(int n) {
    int i = blockIdx.x * blockDim.x + threadIdx.x;
    if (i < n) g_dinv[i] = 1.0f;   // self loop
}
__global__ void k_deg_hist(const int* __restrict__ dst, int E) {
    int e = blockIdx.x * blockDim.x + threadIdx.x;
    if (e < E) atomicAdd(&g_dinv[dst[e]], 1.0f);
}
__global__ void k_deg_rsqrt(int n) {
    int i = blockIdx.x * blockDim.x + threadIdx.x;
    if (i < n) g_dinv[i] = rsqrtf(g_dinv[i]);
}

// ---------------------------------------------------------------------------
// tf32 tensor-core GEMM: C[M,N] = op(A)[M,K] @ W[K,N]
// op = identity or relu(a + bias[k]).
// Block tile 128x64, 256 threads = 8 warps (4 along M x 2 along N),
// each warp 32x32 = 2x2 wmma 16x16x8 tiles. K in chunks of 32.
// M side of C must be padded (caller guarantees C has ceil(M/128)*128 rows).
// ---------------------------------------------------------------------------
#define AS_LD 36
#define BS_LD 68

template <bool RELU_BIAS>
__global__ void k_gemm_tc(const float* __restrict__ A,
                          const float* __restrict__ bias,
                          const float* __restrict__ W,
                          float* __restrict__ C,
                          int M, int K, int N) {
    __shared__ __align__(16) float As[128][AS_LD];  // 128 rows x 32 k (padded)
    __shared__ __align__(16) float Bs[32][BS_LD];   // 32 k x 64 n (padded)

    const int tid = threadIdx.x;
    const int warp = tid >> 5;
    const int warp_m = warp & 3;        // 0..3 -> 32-row slice
    const int warp_n = warp >> 2;       // 0..1 -> 32-col slice
    const int row_base = blockIdx.y * 128;
    const int col_base = blockIdx.x * 64;

    wmma::fragment<wmma::accumulator, 16, 16, 8, float> acc[2][2];
    #pragma unroll
    for (int i = 0; i < 2; i++)
        #pragma unroll
        for (int j = 0; j < 2; j++)
            wmma::fill_fragment(acc[i][j], 0.0f);

    for (int k0 = 0; k0 < K; k0 += 32) {
        // ---- fill A tile: 128 x 32, float4 per thread x4 passes ----
        {
            const int r_in_pass = tid >> 3;      // 0..31
            const int kv = tid & 7;              // float4 index 0..7
            #pragma unroll
            for (int p = 0; p < 4; p++) {
                int r = p * 32 + r_in_pass;
                int grow = row_base + r;
                float4 v = make_float4(0.f, 0.f, 0.f, 0.f);
                if (grow < M) {
                    v = *reinterpret_cast<const float4*>(
                        &A[(size_t)grow * K + k0 + kv * 4]);
                    if (RELU_BIAS) {
                        float4 bb = *reinterpret_cast<const float4*>(&bias[k0 + kv * 4]);
                        v.x = fmaxf(v.x + bb.x, 0.f);
                        v.y = fmaxf(v.y + bb.y, 0.f);
                        v.z = fmaxf(v.z + bb.z, 0.f);
                        v.w = fmaxf(v.w + bb.w, 0.f);
                    }
                }
                *reinterpret_cast<float4*>(&As[r][kv * 4]) = v;
            }
        }
        // ---- fill B tile: 32 x 64, float4 per thread x2 passes ----
        {
            const int kr_in_pass = tid >> 4;     // 0..15
            const int cv = tid & 15;             // float4 index 0..15
            #pragma unroll
            for (int p = 0; p < 2; p++) {
                int kr = p * 16 + kr_in_pass;
                float4 v = *reinterpret_cast<const float4*>(
                    &W[(size_t)(k0 + kr) * N + col_base + cv * 4]);
                *reinterpret_cast<float4*>(&Bs[kr][cv * 4]) = v;
            }
        }
        __syncthreads();

        #pragma unroll
        for (int ks = 0; ks < 4; ks++) {
            wmma::fragment<wmma::matrix_a, 16, 16, 8, wmma::precision::tf32,
                           wmma::row_major> fa[2];
            wmma::fragment<wmma::matrix_b, 16, 16, 8, wmma::precision::tf32,
                           wmma::row_major> fb[2];
            #pragma unroll
            for (int i = 0; i < 2; i++) {
                wmma::load_matrix_sync(fa[i], &As[warp_m * 32 + i * 16][ks * 8], AS_LD);
                #pragma unroll
                for (int t = 0; t < fa[i].num_elements; t++)
                    fa[i].x[t] = wmma::__float_to_tf32(fa[i].x[t]);
            }
            #pragma unroll
            for (int j = 0; j < 2; j++) {
                wmma::load_matrix_sync(fb[j], &Bs[ks * 8][warp_n * 32 + j * 16], BS_LD);
                #pragma unroll
                for (int t = 0; t < fb[j].num_elements; t++)
                    fb[j].x[t] = wmma::__float_to_tf32(fb[j].x[t]);
            }
            #pragma unroll
            for (int i = 0; i < 2; i++)
                #pragma unroll
                for (int j = 0; j < 2; j++)
                    wmma::mma_sync(acc[i][j], fa[i], fb[j], acc[i][j]);
        }
        __syncthreads();
    }

    // store (C rows padded -> no guard)
    #pragma unroll
    for (int i = 0; i < 2; i++)
        #pragma unroll
        for (int j = 0; j < 2; j++) {
            int r = row_base + warp_m * 32 + i * 16;
            int c = col_base + warp_n * 32 + j * 16;
            wmma::store_matrix_sync(&C[(size_t)r * N + c], acc[i][j], N,
                                    wmma::mem_row_major);
        }
}

// ---------------------------------------------------------------------------
// output initializers (self-loop contribution, + bias for layer 2)
// ---------------------------------------------------------------------------
__global__ void k_init_out1(int n) {   // OUT1 = H1 * dinv^2
    size_t idx = (size_t)blockIdx.x * blockDim.x + threadIdx.x;
    size_t total = (size_t)n * D_HID;
    if (idx >= total) return;
    int i = (int)(idx >> 7);
    float dv = g_dinv[i];
    g_OUT1[idx] = g_H1[idx] * dv * dv;
}

__global__ void k_init_out2(const float* __restrict__ b2,
                            float* __restrict__ out, int n) {
    size_t idx = (size_t)blockIdx.x * blockDim.x + threadIdx.x;
    size_t total = (size_t)n * D_OUT;
    if (idx >= total) return;
    int i = (int)(idx >> 6);
    int j = (int)(idx & 63);
    float dv = g_dinv[i];
    out[idx] = b2[j] + g_H2[idx] * dv * dv;
}

// ---------------------------------------------------------------------------
// edge scatter: one thread per (edge, float4 chunk).
//   out[dst] += H[src] * dinv[src]*dinv[dst]
// ---------------------------------------------------------------------------
template <int D4>
__global__ void k_scatter(const float4* __restrict__ H,
                          const int* __restrict__ srcs,
                          const int* __restrict__ dsts,
                          float4* __restrict__ out, int E) {
    long long idx = (long long)blockIdx.x * blockDim.x + threadIdx.x;
    long long e = idx / D4;
    int q = (int)(idx % D4);
    if (e >= E) return;
    int s = __ldg(&srcs[e]);
    int d = __ldg(&dsts[e]);
    float norm = g_dinv[s] * g_dinv[d];
    float4 v = __ldg(&H[(size_t)s * D4 + q]);
    v.x *= norm; v.y *= norm; v.z *= norm; v.w *= norm;
    atomicAdd(&out[(size_t)d * D4 + q], v);
}

// ---------------------------------------------------------------------------
// launch
// ---------------------------------------------------------------------------
extern "C" void kernel_launch(void* const* d_in, const int* in_sizes, int n_in,
                              void* d_out, int out_size) {
    const float* x   = (const float*)d_in[0];
    const int*   ei  = (const int*)d_in[1];    // int32 (JAX x64 disabled)
    const float* W1  = (const float*)d_in[2];
    const float* b1  = (const float*)d_in[3];
    const float* W2  = (const float*)d_in[4];
    const float* b2  = (const float*)d_in[5];
    float*       out = (float*)d_out;

    const int n = in_sizes[0] / D_IN;       // 50000
    const int E = in_sizes[1] / 2;          // 800000
    const int* srcs = ei;
    const int* dsts = ei + E;

    float* H1   = nullptr;
    float* OUT1 = nullptr;
    float* H2   = nullptr;
    cudaGetSymbolAddress((void**)&H1,   g_H1);
    cudaGetSymbolAddress((void**)&OUT1, g_OUT1);
    cudaGetSymbolAddress((void**)&H2,   g_H2);

    const int T = 256;
    const int mblocks = (n + 127) / 128;    // 391

    // 1. normalization
    k_deg_init<<<(n + T - 1) / T, T>>>(n);
    k_deg_hist<<<(E + T - 1) / T, T>>>(dsts, E);
    k_deg_rsqrt<<<(n + T - 1) / T, T>>>(n);

    // 2. GEMM1: H1 = x @ W1   (M=n, K=128, N=128)
    {
        dim3 grid(D_HID / 64, mblocks);
        k_gemm_tc<false><<<grid, 256>>>(x, nullptr, W1, H1, n, D_IN, D_HID);
    }

    // 3. OUT1 init (self loop)
    {
        size_t total = (size_t)n * D_HID;
        k_init_out1<<<(int)((total + T - 1) / T), T>>>(n);
    }

    // 4. scatter layer 1
    {
        long long work = (long long)E * (D_HID / 4);
        k_scatter<D_HID / 4><<<(int)((work + T - 1) / T), T>>>(
            (const float4*)H1, srcs, dsts, (float4*)OUT1, E);
    }

    // 5. GEMM2: H2 = relu(OUT1 + b1) @ W2   (M=n, K=128, N=64)
    {
        dim3 grid(D_OUT / 64, mblocks);
        k_gemm_tc<true><<<grid, 256>>>(OUT1, b1, W2, H2, n, D_HID, D_OUT);
    }

    // 6. OUT init (self loop + bias)
    {
        size_t total = (size_t)n * D_OUT;
        k_init_out2<<<(int)((total + T - 1) / T), T>>>(b2, out, n);
    }

    // 7. scatter layer 2
    {
        long long work = (long long)E * (D_OUT / 4);
        k_scatter<D_OUT / 4><<<(int)((work + T - 1) / T), T>>>(
            (const float4*)H2, srcs, dsts, (float4*)out, E);
    }
}

// round 4
// speedup vs baseline: 2.2107x; 1.5787x over previous
#include <cuda_runtime.h>
#include <cuda_bf16.h>
#include <mma.h>
#include <cstdint>

using namespace nvcuda;

// ---------------------------------------------------------------------------
// GCN 2-layer forward. N=50000, d 128->128->64, E=800000 (+ implicit self loops)
// edge_index int32. tf32 tensor-core GEMMs; atomic-free CSR gather aggregation.
// ---------------------------------------------------------------------------

#define N_NODES 50000
#define M_PAD   50048        // 50000 rounded up to 128
#define D_IN    128
#define D_HID   128
#define D_OUT   64
#define E_MAX   800000
#define NBLK    ((N_NODES + 255) / 256)   // scan blocks = 196

__device__ __align__(16) float g_dinv[N_NODES];
__device__ int   g_count[N_NODES];
__device__ int   g_rowptr[N_NODES + 1];
__device__ int   g_cursor[N_NODES];
__device__ int   g_bsum[NBLK];
__device__ int   g_csr_src[E_MAX];
__device__ float g_csr_w[E_MAX];
__device__ __align__(16) float g_H1[(size_t)M_PAD * D_HID];
__device__ __align__(16) float g_OUT1[(size_t)M_PAD * D_HID];
__device__ __align__(16) float g_H2[(size_t)M_PAD * D_OUT];

// ---------------------------------------------------------------------------
// degree / normalization / CSR build
// ---------------------------------------------------------------------------
__global__ void k_count_zero(int n) {
    int i = blockIdx.x * blockDim.x + threadIdx.x;
    if (i < n) g_count[i] = 0;
}
__global__ void k_deg_hist(const int* __restrict__ dst, int E) {
    int e = blockIdx.x * blockDim.x + threadIdx.x;
    if (e < E) atomicAdd(&g_count[dst[e]], 1);
}
__global__ void k_deg_rsqrt(int n) {
    int i = blockIdx.x * blockDim.x + threadIdx.x;
    if (i < n) g_dinv[i] = rsqrtf(1.0f + (float)g_count[i]);  // +1 self loop
}

// --- 3-kernel exclusive scan of g_count -> g_rowptr ---
__device__ __forceinline__ int warp_iscan(int x, int lane) {
    #pragma unroll
    for (int o = 1; o < 32; o <<= 1) {
        int y = __shfl_up_sync(0xffffffffu, x, o);
        if (lane >= o) x += y;
    }
    return x;
}

__global__ void k_scan1(int n) {
    int i = blockIdx.x * 256 + threadIdx.x;
    int lane = threadIdx.x & 31, w = threadIdx.x >> 5;
    int v = (i < n) ? g_count[i] : 0;
    int x = warp_iscan(v, lane);
    __shared__ int wsum[8];
    if (lane == 31) wsum[w] = x;
    __syncthreads();
    if (w == 0) {
        int s = (lane < 8) ? wsum[lane] : 0;
        #pragma unroll
        for (int o = 1; o < 8; o <<= 1) {
            int y = __shfl_up_sync(0xffffffffu, s, o);
            if (lane >= o) s += y;
        }
        if (lane < 8) wsum[lane] = s;
    }
    __syncthreads();
    int incl = x + ((w > 0) ? wsum[w - 1] : 0);
    if (i < n) g_rowptr[i] = incl - v;              // exclusive within block
    if (threadIdx.x == 255) g_bsum[blockIdx.x] = incl;
}

__global__ void k_scan2(int nb, int n, int E) {     // single block of 256
    int i = threadIdx.x;
    int lane = i & 31, w = i >> 5;
    int v = (i < nb) ? g_bsum[i] : 0;
    int x = warp_iscan(v, lane);
    __shared__ int wsum[8];
    if (lane == 31) wsum[w] = x;
    __syncthreads();
    if (w == 0) {
        int s = (lane < 8) ? wsum[lane] : 0;
        #pragma unroll
        for (int o = 1; o < 8; o <<= 1) {
            int y = __shfl_up_sync(0xffffffffu, s, o);
            if (lane >= o) s += y;
        }
        if (lane < 8) wsum[lane] = s;
    }
    __syncthreads();
    int excl = x + ((w > 0) ? wsum[w - 1] : 0) - v;
    __syncthreads();
    if (i < nb) g_bsum[i] = excl;
    if (i == 0) g_rowptr[n] = E;
}

__global__ void k_scan3(int n) {
    int i = blockIdx.x * 256 + threadIdx.x;
    if (i < n) {
        int r = g_rowptr[i] + g_bsum[blockIdx.x];
        g_rowptr[i] = r;
        g_cursor[i] = r;
    }
}

__global__ void k_bin(const int* __restrict__ src,
                      const int* __restrict__ dst, int E) {
    int e = blockIdx.x * blockDim.x + threadIdx.x;
    if (e >= E) return;
    int s = src[e], d = dst[e];
    int pos = atomicAdd(&g_cursor[d], 1);
    g_csr_src[pos] = s;
    g_csr_w[pos] = g_dinv[s];
}

// ---------------------------------------------------------------------------
// tf32 tensor-core GEMM: C[M,N] = op(A)[M,K] @ W[K,N]
// Block tile 128x64, 8 warps, 2x2 wmma 16x16x8 per warp. K chunks of 32.
// C rows padded to multiple of 128 by caller.
// ---------------------------------------------------------------------------
#define AS_LD 36
#define BS_LD 68

template <bool RELU_BIAS>
__global__ void k_gemm_tc(const float* __restrict__ A,
                          const float* __restrict__ bias,
                          const float* __restrict__ W,
                          float* __restrict__ C,
                          int M, int K, int N) {
    __shared__ __align__(16) float As[128][AS_LD];
    __shared__ __align__(16) float Bs[32][BS_LD];

    const int tid = threadIdx.x;
    const int warp = tid >> 5;
    const int warp_m = warp & 3;
    const int warp_n = warp >> 2;
    const int row_base = blockIdx.y * 128;
    const int col_base = blockIdx.x * 64;

    wmma::fragment<wmma::accumulator, 16, 16, 8, float> acc[2][2];
    #pragma unroll
    for (int i = 0; i < 2; i++)
        #pragma unroll
        for (int j = 0; j < 2; j++)
            wmma::fill_fragment(acc[i][j], 0.0f);

    for (int k0 = 0; k0 < K; k0 += 32) {
        {
            const int r_in_pass = tid >> 3;
            const int kv = tid & 7;
            #pragma unroll
            for (int p = 0; p < 4; p++) {
                int r = p * 32 + r_in_pass;
                int grow = row_base + r;
                float4 v = make_float4(0.f, 0.f, 0.f, 0.f);
                if (grow < M) {
                    v = *reinterpret_cast<const float4*>(
                        &A[(size_t)grow * K + k0 + kv * 4]);
                    if (RELU_BIAS) {
                        float4 bb = *reinterpret_cast<const float4*>(&bias[k0 + kv * 4]);
                        v.x = fmaxf(v.x + bb.x, 0.f);
                        v.y = fmaxf(v.y + bb.y, 0.f);
                        v.z = fmaxf(v.z + bb.z, 0.f);
                        v.w = fmaxf(v.w + bb.w, 0.f);
                    }
                }
                *reinterpret_cast<float4*>(&As[r][kv * 4]) = v;
            }
        }
        {
            const int kr_in_pass = tid >> 4;
            const int cv = tid & 15;
            #pragma unroll
            for (int p = 0; p < 2; p++) {
                int kr = p * 16 + kr_in_pass;
                float4 v = *reinterpret_cast<const float4*>(
                    &W[(size_t)(k0 + kr) * N + col_base + cv * 4]);
                *reinterpret_cast<float4*>(&Bs[kr][cv * 4]) = v;
            }
        }
        __syncthreads();

        #pragma unroll
        for (int ks = 0; ks < 4; ks++) {
            wmma::fragment<wmma::matrix_a, 16, 16, 8, wmma::precision::tf32,
                           wmma::row_major> fa[2];
            wmma::fragment<wmma::matrix_b, 16, 16, 8, wmma::precision::tf32,
                           wmma::row_major> fb[2];
            #pragma unroll
            for (int i = 0; i < 2; i++) {
                wmma::load_matrix_sync(fa[i], &As[warp_m * 32 + i * 16][ks * 8], AS_LD);
                #pragma unroll
                for (int t = 0; t < fa[i].num_elements; t++)
                    fa[i].x[t] = wmma::__float_to_tf32(fa[i].x[t]);
            }
            #pragma unroll
            for (int j = 0; j < 2; j++) {
                wmma::load_matrix_sync(fb[j], &Bs[ks * 8][warp_n * 32 + j * 16], BS_LD);
                #pragma unroll
                for (int t = 0; t < fb[j].num_elements; t++)
                    fb[j].x[t] = wmma::__float_to_tf32(fb[j].x[t]);
            }
            #pragma unroll
            for (int i = 0; i < 2; i++)
                #pragma unroll
                for (int j = 0; j < 2; j++)
                    wmma::mma_sync(acc[i][j], fa[i], fb[j], acc[i][j]);
        }
        __syncthreads();
    }

    #pragma unroll
    for (int i = 0; i < 2; i++)
        #pragma unroll
        for (int j = 0; j < 2; j++) {
            int r = row_base + warp_m * 32 + i * 16;
            int c = col_base + warp_n * 32 + j * 16;
            wmma::store_matrix_sync(&C[(size_t)r * N + c], acc[i][j], N,
                                    wmma::mem_row_major);
        }
}

// ---------------------------------------------------------------------------
// CSR gather aggregation (atomic-free). TPN = D/4 lanes per node; each lane
// owns one float4 column. Self loop (dinv^2) is the accumulator init; layer-2
// adds bias at the end.
//   out[i] = (bias) + H[i]*dinv[i]^2 + sum_e H[src_e] * w_e * dinv[i]
// ---------------------------------------------------------------------------
template <int TPN, bool BIAS>
__global__ void k_agg(const float4* __restrict__ H,
                      const float* __restrict__ bias,
                      float4* __restrict__ out, int n) {
    int t = blockIdx.x * blockDim.x + threadIdx.x;
    int node = t / TPN;
    int q = t % TPN;
    if (node >= n) return;

    float dv = g_dinv[node];
    int beg = __ldg(&g_rowptr[node]);
    int end = __ldg(&g_rowptr[node + 1]);

    float4 h = __ldg(&H[(size_t)node * TPN + q]);
    float self = dv * dv;
    float4 acc = make_float4(h.x * self, h.y * self, h.z * self, h.w * self);

    for (int e = beg; e < end; e++) {
        int s = __ldg(&g_csr_src[e]);
        float w = __ldg(&g_csr_w[e]) * dv;
        float4 v = __ldg(&H[(size_t)s * TPN + q]);
        acc.x = fmaf(v.x, w, acc.x);
        acc.y = fmaf(v.y, w, acc.y);
        acc.z = fmaf(v.z, w, acc.z);
        acc.w = fmaf(v.w, w, acc.w);
    }
    if (BIAS) {
        float4 bb = *reinterpret_cast<const float4*>(&bias[q * 4]);
        acc.x += bb.x; acc.y += bb.y; acc.z += bb.z; acc.w += bb.w;
    }
    out[(size_t)node * TPN + q] = acc;
}

// ---------------------------------------------------------------------------
// launch
// ---------------------------------------------------------------------------
extern "C" void kernel_launch(void* const* d_in, const int* in_sizes, int n_in,
                              void* d_out, int out_size) {
    const float* x   = (const float*)d_in[0];
    const int*   ei  = (const int*)d_in[1];    // int32 (JAX x64 disabled)
    const float* W1  = (const float*)d_in[2];
    const float* b1  = (const float*)d_in[3];
    const float* W2  = (const float*)d_in[4];
    const float* b2  = (const float*)d_in[5];
    float*       out = (float*)d_out;

    const int n = in_sizes[0] / D_IN;       // 50000
    const int E = in_sizes[1] / 2;          // 800000
    const int* srcs = ei;
    const int* dsts = ei + E;

    float* H1   = nullptr;
    float* OUT1 = nullptr;
    float* H2   = nullptr;
    cudaGetSymbolAddress((void**)&H1,   g_H1);
    cudaGetSymbolAddress((void**)&OUT1, g_OUT1);
    cudaGetSymbolAddress((void**)&H2,   g_H2);

    const int T = 256;
    const int nb = (n + T - 1) / T;         // 196
    const int mblocks = (n + 127) / 128;    // 391

    // 1. degree + dinv + CSR
    k_count_zero<<<nb, T>>>(n);
    k_deg_hist<<<(E + T - 1) / T, T>>>(dsts, E);
    k_deg_rsqrt<<<nb, T>>>(n);
    k_scan1<<<nb, T>>>(n);
    k_scan2<<<1, T>>>(nb, n, E);
    k_scan3<<<nb, T>>>(n);
    k_bin<<<(E + T - 1) / T, T>>>(srcs, dsts, E);

    // 2. GEMM1: H1 = x @ W1
    {
        dim3 grid(D_HID / 64, mblocks);
        k_gemm_tc<false><<<grid, 256>>>(x, nullptr, W1, H1, n, D_IN, D_HID);
    }

    // 3. aggregation layer 1 (self loop folded in)
    {
        long long work = (long long)n * (D_HID / 4);
        k_agg<D_HID / 4, false><<<(int)((work + T - 1) / T), T>>>(
            (const float4*)H1, nullptr, (float4*)OUT1, n);
    }

    // 4. GEMM2: H2 = relu(OUT1 + b1) @ W2
    {
        dim3 grid(D_OUT / 64, mblocks);
        k_gemm_tc<true><<<grid, 256>>>(OUT1, b1, W2, H2, n, D_HID, D_OUT);
    }

    // 5. aggregation layer 2 (self loop + b2 folded in)
    {
        long long work = (long long)n * (D_OUT / 4);
        k_agg<D_OUT / 4, true><<<(int)((work + T - 1) / T), T>>>(
            (const float4*)H2, b2, (float4*)out, n);
    }
}

// round 5
// speedup vs baseline: 2.3016x; 1.0411x over previous
#include <cuda_runtime.h>
#include <cuda_bf16.h>
#include <mma.h>
#include <cstdint>

using namespace nvcuda;

// ---------------------------------------------------------------------------
// GCN 2-layer forward. N=50000, d 128->128->64, E=800000 (+ implicit self loops)
// edge_index int32. tf32 tensor-core GEMMs (cp.async 2-stage pipeline);
// atomic-free CSR gather aggregation with fused bias/relu epilogues.
// ---------------------------------------------------------------------------

#define N_NODES 50000
#define M_PAD   50048
#define D_IN    128
#define D_HID   128
#define D_OUT   64
#define E_MAX   800000
#define NBLK    ((N_NODES + 255) / 256)   // 196

__device__ __align__(16) float g_dinv[N_NODES];
__device__ int   g_count[N_NODES];
__device__ int   g_rowptr[N_NODES + 1];
__device__ int   g_cursor[N_NODES];
__device__ int   g_bsum[NBLK];
__device__ int   g_csr_src[E_MAX];
__device__ float g_csr_w[E_MAX];
__device__ __align__(16) float g_H1[(size_t)M_PAD * D_HID];
__device__ __align__(16) float g_OUT1[(size_t)M_PAD * D_HID];
__device__ __align__(16) float g_H2[(size_t)M_PAD * D_OUT];

// ---------------------------------------------------------------------------
// cp.async helpers
// ---------------------------------------------------------------------------
__device__ __forceinline__ void cp_async16(void* smem, const void* gmem, int srcbytes) {
    uint32_t s = (uint32_t)__cvta_generic_to_shared(smem);
    asm volatile("cp.async.cg.shared.global [%0], [%1], 16, %2;\n"
                 :: "r"(s), "l"(gmem), "r"(srcbytes));
}
__device__ __forceinline__ void cp_commit() {
    asm volatile("cp.async.commit_group;\n");
}
template <int N>
__device__ __forceinline__ void cp_wait() {
    asm volatile("cp.async.wait_group %0;\n" :: "n"(N));
}

// ---------------------------------------------------------------------------
// degree + dinv + CSR build
// ---------------------------------------------------------------------------
__global__ void k_deg_hist(const int* __restrict__ dst, int E) {
    int e = blockIdx.x * blockDim.x + threadIdx.x;
    if (e < E) atomicAdd(&g_count[dst[e]], 1);
}

__device__ __forceinline__ int warp_iscan(int x, int lane) {
    #pragma unroll
    for (int o = 1; o < 32; o <<= 1) {
        int y = __shfl_up_sync(0xffffffffu, x, o);
        if (lane >= o) x += y;
    }
    return x;
}

// block-level exclusive scan of counts -> rowptr (local), block sums -> bsum,
// fused dinv computation.
__global__ void k_scan1(int n) {
    int i = blockIdx.x * 256 + threadIdx.x;
    int lane = threadIdx.x & 31, w = threadIdx.x >> 5;
    int v = (i < n) ? g_count[i] : 0;
    if (i < n) g_dinv[i] = rsqrtf(1.0f + (float)v);   // +1 self loop
    int x = warp_iscan(v, lane);
    __shared__ int wsum[8];
    if (lane == 31) wsum[w] = x;
    __syncthreads();
    if (w == 0) {
        int s = (lane < 8) ? wsum[lane] : 0;
        #pragma unroll
        for (int o = 1; o < 8; o <<= 1) {
            int y = __shfl_up_sync(0xffffffffu, s, o);
            if (lane >= o) s += y;
        }
        if (lane < 8) wsum[lane] = s;
    }
    __syncthreads();
    int incl = x + ((w > 0) ? wsum[w - 1] : 0);
    if (i < n) g_rowptr[i] = incl - v;
    if (threadIdx.x == 255) g_bsum[blockIdx.x] = incl;
}

// every block redundantly scans the 196 block sums, then applies its offset
// to its 256-node chunk; also inits cursors and rowptr[n].
__global__ void k_scan2apply(int n, int E) {
    int t = threadIdx.x;
    int lane = t & 31, w = t >> 5;
    int v = (t < NBLK) ? g_bsum[t] : 0;
    int x = warp_iscan(v, lane);
    __shared__ int wsum[8];
    __shared__ int sb[256];
    if (lane == 31) wsum[w] = x;
    __syncthreads();
    if (w == 0) {
        int s = (lane < 8) ? wsum[lane] : 0;
        #pragma unroll
        for (int o = 1; o < 8; o <<= 1) {
            int y = __shfl_up_sync(0xffffffffu, s, o);
            if (lane >= o) s += y;
        }
        if (lane < 8) wsum[lane] = s;
    }
    __syncthreads();
    sb[t] = x + ((w > 0) ? wsum[w - 1] : 0) - v;      // exclusive
    __syncthreads();

    int i = blockIdx.x * 256 + t;
    if (i < n) {
        int r = g_rowptr[i] + sb[blockIdx.x];
        g_rowptr[i] = r;
        g_cursor[i] = r;
    }
    if (i == n) g_rowptr[n] = E;                      // block 195 covers i=n? n=50000, last i=50175 -> yes
}

__global__ void k_bin(const int* __restrict__ src,
                      const int* __restrict__ dst, int E) {
    int e = blockIdx.x * blockDim.x + threadIdx.x;
    if (e >= E) return;
    int s = src[e], d = dst[e];
    int pos = atomicAdd(&g_cursor[d], 1);
    g_csr_src[pos] = s;
    g_csr_w[pos] = g_dinv[s];
}

// ---------------------------------------------------------------------------
// tf32 tensor-core GEMM with cp.async 2-stage pipeline.
// C[M,N] = A[M,K] @ W[K,N].  Block tile 128x64, 8 warps, 2x2 wmma 16x16x8
// per warp, K chunks of 32. C rows padded; A OOB rows zero-filled.
// Dynamic smem: 2*(128*AS_LD + 32*BS_LD)*4 bytes.
// ---------------------------------------------------------------------------
#define AS_LD 36
#define BS_LD 68
#define GEMM_SMEM (2 * (128 * AS_LD + 32 * BS_LD) * 4)

__global__ void __launch_bounds__(256)
k_gemm_tc(const float* __restrict__ A,
          const float* __restrict__ W,
          float* __restrict__ C,
          int M, int K, int N) {
    extern __shared__ __align__(16) float smem[];
    float (*As)[128][AS_LD] = reinterpret_cast<float (*)[128][AS_LD]>(smem);
    float (*Bs)[32][BS_LD]  = reinterpret_cast<float (*)[32][BS_LD]>(smem + 2 * 128 * AS_LD);

    const int tid = threadIdx.x;
    const int warp = tid >> 5;
    const int warp_m = warp & 3;
    const int warp_n = warp >> 2;
    const int row_base = blockIdx.y * 128;
    const int col_base = blockIdx.x * 64;

    const int a_r = tid >> 3;          // 0..31 (A rows per pass)
    const int a_kv = tid & 7;          // float4 col in chunk
    const int b_kr = tid >> 4;         // 0..15 (B k-rows per pass)
    const int b_cv = tid & 15;         // float4 col

    const int nchunks = K >> 5;        // K/32

    // prefetch chunk 0 into stage 0
    auto load_chunk = [&](int c, int buf) {
        int k0 = c << 5;
        #pragma unroll
        for (int p = 0; p < 4; p++) {
            int r = p * 32 + a_r;
            int grow = row_base + r;
            int ok = (grow < M) ? 16 : 0;
            int ga = (grow < M) ? grow : (M - 1);
            cp_async16(&As[buf][r][a_kv * 4],
                       &A[(size_t)ga * K + k0 + a_kv * 4], ok);
        }
        #pragma unroll
        for (int p = 0; p < 2; p++) {
            int kr = p * 16 + b_kr;
            cp_async16(&Bs[buf][kr][b_cv * 4],
                       &W[(size_t)(k0 + kr) * N + col_base + b_cv * 4], 16);
        }
    };

    wmma::fragment<wmma::accumulator, 16, 16, 8, float> acc[2][2];
    #pragma unroll
    for (int i = 0; i < 2; i++)
        #pragma unroll
        for (int j = 0; j < 2; j++)
            wmma::fill_fragment(acc[i][j], 0.0f);

    load_chunk(0, 0);
    cp_commit();

    for (int c = 0; c < nchunks; c++) {
        if (c + 1 < nchunks) {
            load_chunk(c + 1, (c + 1) & 1);
            cp_commit();
            cp_wait<1>();
        } else {
            cp_wait<0>();
        }
        __syncthreads();

        int buf = c & 1;
        #pragma unroll
        for (int ks = 0; ks < 4; ks++) {
            wmma::fragment<wmma::matrix_a, 16, 16, 8, wmma::precision::tf32,
                           wmma::row_major> fa[2];
            wmma::fragment<wmma::matrix_b, 16, 16, 8, wmma::precision::tf32,
                           wmma::row_major> fb[2];
            #pragma unroll
            for (int i = 0; i < 2; i++) {
                wmma::load_matrix_sync(fa[i], &As[buf][warp_m * 32 + i * 16][ks * 8], AS_LD);
                #pragma unroll
                for (int t = 0; t < fa[i].num_elements; t++)
                    fa[i].x[t] = wmma::__float_to_tf32(fa[i].x[t]);
            }
            #pragma unroll
            for (int j = 0; j < 2; j++) {
                wmma::load_matrix_sync(fb[j], &Bs[buf][ks * 8][warp_n * 32 + j * 16], BS_LD);
                #pragma unroll
                for (int t = 0; t < fb[j].num_elements; t++)
                    fb[j].x[t] = wmma::__float_to_tf32(fb[j].x[t]);
            }
            #pragma unroll
            for (int i = 0; i < 2; i++)
                #pragma unroll
                for (int j = 0; j < 2; j++)
                    wmma::mma_sync(acc[i][j], fa[i], fb[j], acc[i][j]);
        }
        __syncthreads();
    }

    #pragma unroll
    for (int i = 0; i < 2; i++)
        #pragma unroll
        for (int j = 0; j < 2; j++) {
            int r = row_base + warp_m * 32 + i * 16;
            int c2 = col_base + warp_n * 32 + j * 16;
            wmma::store_matrix_sync(&C[(size_t)r * N + c2], acc[i][j], N,
                                    wmma::mem_row_major);
        }
}

// ---------------------------------------------------------------------------
// CSR gather aggregation. TPN lanes per node, one float4 column each.
//   acc = H[i]*dinv^2 + sum_e H[src_e]*w_e*dinv ;  out = RELU? relu(acc+b) : acc+b
// ---------------------------------------------------------------------------
template <int TPN, bool RELU>
__global__ void k_agg(const float4* __restrict__ H,
                      const float* __restrict__ bias,
                      float4* __restrict__ out, int n) {
    int t = blockIdx.x * blockDim.x + threadIdx.x;
    int node = t / TPN;
    int q = t % TPN;
    if (node >= n) return;

    float dv = g_dinv[node];
    int beg = __ldg(&g_rowptr[node]);
    int end = __ldg(&g_rowptr[node + 1]);

    float4 h = __ldg(&H[(size_t)node * TPN + q]);
    float self = dv * dv;
    float4 acc = make_float4(h.x * self, h.y * self, h.z * self, h.w * self);

    for (int e = beg; e < end; e++) {
        int s = __ldg(&g_csr_src[e]);
        float w = __ldg(&g_csr_w[e]) * dv;
        float4 v = __ldg(&H[(size_t)s * TPN + q]);
        acc.x = fmaf(v.x, w, acc.x);
        acc.y = fmaf(v.y, w, acc.y);
        acc.z = fmaf(v.z, w, acc.z);
        acc.w = fmaf(v.w, w, acc.w);
    }
    float4 bb = *reinterpret_cast<const float4*>(&bias[q * 4]);
    acc.x += bb.x; acc.y += bb.y; acc.z += bb.z; acc.w += bb.w;
    if (RELU) {
        acc.x = fmaxf(acc.x, 0.f); acc.y = fmaxf(acc.y, 0.f);
        acc.z = fmaxf(acc.z, 0.f); acc.w = fmaxf(acc.w, 0.f);
    }
    out[(size_t)node * TPN + q] = acc;
}

// ---------------------------------------------------------------------------
// launch
// ---------------------------------------------------------------------------
extern "C" void kernel_launch(void* const* d_in, const int* in_sizes, int n_in,
                              void* d_out, int out_size) {
    const float* x   = (const float*)d_in[0];
    const int*   ei  = (const int*)d_in[1];    // int32 (JAX x64 disabled)
    const float* W1  = (const float*)d_in[2];
    const float* b1  = (const float*)d_in[3];
    const float* W2  = (const float*)d_in[4];
    const float* b2  = (const float*)d_in[5];
    float*       out = (float*)d_out;

    const int n = in_sizes[0] / D_IN;       // 50000
    const int E = in_sizes[1] / 2;          // 800000
    const int* srcs = ei;
    const int* dsts = ei + E;

    float* H1 = nullptr; float* OUT1 = nullptr; float* H2 = nullptr;
    int*   cnt = nullptr;
    cudaGetSymbolAddress((void**)&H1,   g_H1);
    cudaGetSymbolAddress((void**)&OUT1, g_OUT1);
    cudaGetSymbolAddress((void**)&H2,   g_H2);
    cudaGetSymbolAddress((void**)&cnt,  g_count);

    static bool attr_set = false;
    if (!attr_set) {
        cudaFuncSetAttribute(k_gemm_tc,
                             cudaFuncAttributeMaxDynamicSharedMemorySize, GEMM_SMEM);
        attr_set = true;
    }

    const int T = 256;
    const int nb = (n + T - 1) / T;         // 196
    const int mblocks = (n + 127) / 128;    // 391

    // 1. degree + dinv + CSR  (5 nodes)
    cudaMemsetAsync(cnt, 0, (size_t)n * sizeof(int));
    k_deg_hist<<<(E + T - 1) / T, T>>>(dsts, E);
    k_scan1<<<nb, T>>>(n);
    k_scan2apply<<<nb, T>>>(n, E);
    k_bin<<<(E + T - 1) / T, T>>>(srcs, dsts, E);

    // 2. GEMM1: H1 = x @ W1
    {
        dim3 grid(D_HID / 64, mblocks);
        k_gemm_tc<<<grid, 256, GEMM_SMEM>>>(x, W1, H1, n, D_IN, D_HID);
    }

    // 3. aggregation layer 1: OUT1 = relu(agg(H1) + b1)
    {
        long long work = (long long)n * (D_HID / 4);
        k_agg<D_HID / 4, true><<<(int)((work + T - 1) / T), T>>>(
            (const float4*)H1, b1, (float4*)OUT1, n);
    }

    // 4. GEMM2: H2 = OUT1 @ W2
    {
        dim3 grid(D_OUT / 64, mblocks);
        k_gemm_tc<<<grid, 256, GEMM_SMEM>>>(OUT1, W2, H2, n, D_HID, D_OUT);
    }

    // 5. aggregation layer 2: out = agg(H2) + b2
    {
        long long work = (long long)n * (D_OUT / 4);
        k_agg<D_OUT / 4, false><<<(int)((work + T - 1) / T), T>>>(
            (const float4*)H2, b2, (float4*)out, n);
    }
}

// round 6
// speedup vs baseline: 2.4697x; 1.0730x over previous
#include <cuda_runtime.h>
#include <cuda_bf16.h>
#include <mma.h>
#include <cstdint>

using namespace nvcuda;

// ---------------------------------------------------------------------------
// GCN 2-layer forward. N=50000, d 128->128->64, E=800000 (+ implicit self loops)
// edge_index int32. tf32 tensor-core GEMMs (cp.async pipeline); atomic-free
// CSR gather aggregation. CSR build overlapped with GEMM1 via stream fork.
// ---------------------------------------------------------------------------

#define N_NODES 50000
#define M_PAD   50048
#define D_IN    128
#define D_HID   128
#define D_OUT   64
#define E_MAX   800000
#define NBLK    ((N_NODES + 255) / 256)   // 196

__device__ __align__(16) float g_dinv[N_NODES];
__device__ int   g_count[N_NODES];
__device__ int   g_rowptr[N_NODES + 1];
__device__ int   g_cursor[N_NODES];
__device__ int   g_bsum[NBLK];
__device__ __align__(16) int2 g_csr[E_MAX];        // {src, weight bits}
__device__ __align__(16) float g_H1[(size_t)M_PAD * D_HID];
__device__ __align__(16) float g_OUT1[(size_t)M_PAD * D_HID];
__device__ __align__(16) float g_H2[(size_t)M_PAD * D_OUT];

// ---------------------------------------------------------------------------
// cp.async helpers
// ---------------------------------------------------------------------------
__device__ __forceinline__ void cp_async16(void* smem, const void* gmem, int srcbytes) {
    uint32_t s = (uint32_t)__cvta_generic_to_shared(smem);
    asm volatile("cp.async.cg.shared.global [%0], [%1], 16, %2;\n"
                 :: "r"(s), "l"(gmem), "r"(srcbytes));
}
__device__ __forceinline__ void cp_commit() {
    asm volatile("cp.async.commit_group;\n");
}
template <int N>
__device__ __forceinline__ void cp_wait() {
    asm volatile("cp.async.wait_group %0;\n" :: "n"(N));
}

// ---------------------------------------------------------------------------
// degree + dinv + CSR build
// ---------------------------------------------------------------------------
__global__ void k_deg_hist(const int* __restrict__ dst, int E) {
    int e = blockIdx.x * blockDim.x + threadIdx.x;
    if (e < E) atomicAdd(&g_count[dst[e]], 1);
}

__device__ __forceinline__ int warp_iscan(int x, int lane) {
    #pragma unroll
    for (int o = 1; o < 32; o <<= 1) {
        int y = __shfl_up_sync(0xffffffffu, x, o);
        if (lane >= o) x += y;
    }
    return x;
}

__global__ void k_scan1(int n) {
    int i = blockIdx.x * 256 + threadIdx.x;
    int lane = threadIdx.x & 31, w = threadIdx.x >> 5;
    int v = (i < n) ? g_count[i] : 0;
    if (i < n) g_dinv[i] = rsqrtf(1.0f + (float)v);   // +1 self loop
    int x = warp_iscan(v, lane);
    __shared__ int wsum[8];
    if (lane == 31) wsum[w] = x;
    __syncthreads();
    if (w == 0) {
        int s = (lane < 8) ? wsum[lane] : 0;
        #pragma unroll
        for (int o = 1; o < 8; o <<= 1) {
            int y = __shfl_up_sync(0xffffffffu, s, o);
            if (lane >= o) s += y;
        }
        if (lane < 8) wsum[lane] = s;
    }
    __syncthreads();
    int incl = x + ((w > 0) ? wsum[w - 1] : 0);
    if (i < n) g_rowptr[i] = incl - v;
    if (threadIdx.x == 255) g_bsum[blockIdx.x] = incl;
}

// every block redundantly scans the 196 block sums, applies its offset,
// inits cursors and rowptr[n].
__global__ void k_scan2apply(int n, int E) {
    int t = threadIdx.x;
    int lane = t & 31, w = t >> 5;
    int v = (t < NBLK) ? g_bsum[t] : 0;
    int x = warp_iscan(v, lane);
    __shared__ int wsum[8];
    __shared__ int sb[256];
    if (lane == 31) wsum[w] = x;
    __syncthreads();
    if (w == 0) {
        int s = (lane < 8) ? wsum[lane] : 0;
        #pragma unroll
        for (int o = 1; o < 8; o <<= 1) {
            int y = __shfl_up_sync(0xffffffffu, s, o);
            if (lane >= o) s += y;
        }
        if (lane < 8) wsum[lane] = s;
    }
    __syncthreads();
    sb[t] = x + ((w > 0) ? wsum[w - 1] : 0) - v;
    __syncthreads();

    int i = blockIdx.x * 256 + t;
    if (i < n) {
        int r = g_rowptr[i] + sb[blockIdx.x];
        g_rowptr[i] = r;
        g_cursor[i] = r;
    }
    if (i == n) g_rowptr[n] = E;
}

__global__ void k_bin(const int* __restrict__ src,
                      const int* __restrict__ dst, int E) {
    int e = blockIdx.x * blockDim.x + threadIdx.x;
    if (e >= E) return;
    int s = src[e], d = dst[e];
    int pos = atomicAdd(&g_cursor[d], 1);
    g_csr[pos] = make_int2(s, __float_as_int(g_dinv[s]));
}

// ---------------------------------------------------------------------------
// tf32 tensor-core GEMM with cp.async 2-stage pipeline. 128x64 tile, 8 warps.
// ---------------------------------------------------------------------------
#define AS_LD 36
#define BS_LD 68
#define GEMM_SMEM (2 * (128 * AS_LD + 32 * BS_LD) * 4)

__global__ void __launch_bounds__(256)
k_gemm_tc(const float* __restrict__ A,
          const float* __restrict__ W,
          float* __restrict__ C,
          int M, int K, int N) {
    extern __shared__ __align__(16) float smem[];
    float (*As)[128][AS_LD] = reinterpret_cast<float (*)[128][AS_LD]>(smem);
    float (*Bs)[32][BS_LD]  = reinterpret_cast<float (*)[32][BS_LD]>(smem + 2 * 128 * AS_LD);

    const int tid = threadIdx.x;
    const int warp = tid >> 5;
    const int warp_m = warp & 3;
    const int warp_n = warp >> 2;
    const int row_base = blockIdx.y * 128;
    const int col_base = blockIdx.x * 64;

    const int a_r = tid >> 3;
    const int a_kv = tid & 7;
    const int b_kr = tid >> 4;
    const int b_cv = tid & 15;

    const int nchunks = K >> 5;

    auto load_chunk = [&](int c, int buf) {
        int k0 = c << 5;
        #pragma unroll
        for (int p = 0; p < 4; p++) {
            int r = p * 32 + a_r;
            int grow = row_base + r;
            int ok = (grow < M) ? 16 : 0;
            int ga = (grow < M) ? grow : (M - 1);
            cp_async16(&As[buf][r][a_kv * 4],
                       &A[(size_t)ga * K + k0 + a_kv * 4], ok);
        }
        #pragma unroll
        for (int p = 0; p < 2; p++) {
            int kr = p * 16 + b_kr;
            cp_async16(&Bs[buf][kr][b_cv * 4],
                       &W[(size_t)(k0 + kr) * N + col_base + b_cv * 4], 16);
        }
    };

    wmma::fragment<wmma::accumulator, 16, 16, 8, float> acc[2][2];
    #pragma unroll
    for (int i = 0; i < 2; i++)
        #pragma unroll
        for (int j = 0; j < 2; j++)
            wmma::fill_fragment(acc[i][j], 0.0f);

    load_chunk(0, 0);
    cp_commit();

    for (int c = 0; c < nchunks; c++) {
        if (c + 1 < nchunks) {
            load_chunk(c + 1, (c + 1) & 1);
            cp_commit();
            cp_wait<1>();
        } else {
            cp_wait<0>();
        }
        __syncthreads();

        int buf = c & 1;
        #pragma unroll
        for (int ks = 0; ks < 4; ks++) {
            wmma::fragment<wmma::matrix_a, 16, 16, 8, wmma::precision::tf32,
                           wmma::row_major> fa[2];
            wmma::fragment<wmma::matrix_b, 16, 16, 8, wmma::precision::tf32,
                           wmma::row_major> fb[2];
            #pragma unroll
            for (int i = 0; i < 2; i++) {
                wmma::load_matrix_sync(fa[i], &As[buf][warp_m * 32 + i * 16][ks * 8], AS_LD);
                #pragma unroll
                for (int t = 0; t < fa[i].num_elements; t++)
                    fa[i].x[t] = wmma::__float_to_tf32(fa[i].x[t]);
            }
            #pragma unroll
            for (int j = 0; j < 2; j++) {
                wmma::load_matrix_sync(fb[j], &Bs[buf][ks * 8][warp_n * 32 + j * 16], BS_LD);
                #pragma unroll
                for (int t = 0; t < fb[j].num_elements; t++)
                    fb[j].x[t] = wmma::__float_to_tf32(fb[j].x[t]);
            }
            #pragma unroll
            for (int i = 0; i < 2; i++)
                #pragma unroll
                for (int j = 0; j < 2; j++)
                    wmma::mma_sync(acc[i][j], fa[i], fb[j], acc[i][j]);
        }
        __syncthreads();
    }

    #pragma unroll
    for (int i = 0; i < 2; i++)
        #pragma unroll
        for (int j = 0; j < 2; j++) {
            int r = row_base + warp_m * 32 + i * 16;
            int c2 = col_base + warp_n * 32 + j * 16;
            wmma::store_matrix_sync(&C[(size_t)r * N + c2], acc[i][j], N,
                                    wmma::mem_row_major);
        }
}

// ---------------------------------------------------------------------------
// CSR gather aggregation. TPN lanes per node, one float4 column each.
// Next-edge prefetch breaks the ld->ld->fma chain.
// ---------------------------------------------------------------------------
template <int TPN, bool RELU>
__global__ void k_agg(const float4* __restrict__ H,
                      const float* __restrict__ bias,
                      float4* __restrict__ out, int n) {
    int t = blockIdx.x * blockDim.x + threadIdx.x;
    int node = t / TPN;
    int q = t % TPN;
    if (node >= n) return;

    float dv = g_dinv[node];
    int beg = __ldg(&g_rowptr[node]);
    int end = __ldg(&g_rowptr[node + 1]);

    float4 h = __ldg(&H[(size_t)node * TPN + q]);
    float self = dv * dv;
    float4 acc = make_float4(h.x * self, h.y * self, h.z * self, h.w * self);

    if (beg < end) {
        int2 cur = __ldg(&g_csr[beg]);
        for (int e = beg; e < end; e++) {
            int2 nxt = (e + 1 < end) ? __ldg(&g_csr[e + 1]) : cur;
            float w = __int_as_float(cur.y) * dv;
            float4 v = __ldg(&H[(size_t)cur.x * TPN + q]);
            acc.x = fmaf(v.x, w, acc.x);
            acc.y = fmaf(v.y, w, acc.y);
            acc.z = fmaf(v.z, w, acc.z);
            acc.w = fmaf(v.w, w, acc.w);
            cur = nxt;
        }
    }
    float4 bb = *reinterpret_cast<const float4*>(&bias[q * 4]);
    acc.x += bb.x; acc.y += bb.y; acc.z += bb.z; acc.w += bb.w;
    if (RELU) {
        acc.x = fmaxf(acc.x, 0.f); acc.y = fmaxf(acc.y, 0.f);
        acc.z = fmaxf(acc.z, 0.f); acc.w = fmaxf(acc.w, 0.f);
    }
    out[(size_t)node * TPN + q] = acc;
}

// ---------------------------------------------------------------------------
// launch: CSR build on capture stream, GEMM1 forked onto side stream.
// ---------------------------------------------------------------------------
extern "C" void kernel_launch(void* const* d_in, const int* in_sizes, int n_in,
                              void* d_out, int out_size) {
    const float* x   = (const float*)d_in[0];
    const int*   ei  = (const int*)d_in[1];    // int32 (JAX x64 disabled)
    const float* W1  = (const float*)d_in[2];
    const float* b1  = (const float*)d_in[3];
    const float* W2  = (const float*)d_in[4];
    const float* b2  = (const float*)d_in[5];
    float*       out = (float*)d_out;

    const int n = in_sizes[0] / D_IN;       // 50000
    const int E = in_sizes[1] / 2;          // 800000
    const int* srcs = ei;
    const int* dsts = ei + E;

    float* H1 = nullptr; float* OUT1 = nullptr; float* H2 = nullptr;
    int*   cnt = nullptr;
    cudaGetSymbolAddress((void**)&H1,   g_H1);
    cudaGetSymbolAddress((void**)&OUT1, g_OUT1);
    cudaGetSymbolAddress((void**)&H2,   g_H2);
    cudaGetSymbolAddress((void**)&cnt,  g_count);

    static cudaStream_t s1 = nullptr;
    static cudaEvent_t  evFork = nullptr, evJoin = nullptr;
    if (!s1) {
        cudaFuncSetAttribute(k_gemm_tc,
                             cudaFuncAttributeMaxDynamicSharedMemorySize, GEMM_SMEM);
        cudaStreamCreateWithFlags(&s1, cudaStreamNonBlocking);
        cudaEventCreateWithFlags(&evFork, cudaEventDisableTiming);
        cudaEventCreateWithFlags(&evJoin, cudaEventDisableTiming);
    }

    const int T = 256;
    const int nb = (n + T - 1) / T;         // 196
    const int mblocks = (n + 127) / 128;    // 391

    // ---- fork: GEMM1 on s1, concurrent with CSR build on stream 0 ----
    cudaEventRecord(evFork, 0);
    cudaStreamWaitEvent(s1, evFork, 0);
    {
        dim3 grid(D_HID / 64, mblocks);
        k_gemm_tc<<<grid, 256, GEMM_SMEM, s1>>>(x, W1, H1, n, D_IN, D_HID);
    }
    cudaEventRecord(evJoin, s1);

    // ---- CSR build on capture stream ----
    cudaMemsetAsync(cnt, 0, (size_t)n * sizeof(int));
    k_deg_hist<<<(E + T - 1) / T, T>>>(dsts, E);
    k_scan1<<<nb, T>>>(n);
    k_scan2apply<<<nb, T>>>(n, E);
    k_bin<<<(E + T - 1) / T, T>>>(srcs, dsts, E);

    // ---- join: agg1 needs both H1 and CSR ----
    cudaStreamWaitEvent(0, evJoin, 0);

    // aggregation layer 1: OUT1 = relu(agg(H1) + b1)
    {
        long long work = (long long)n * (D_HID / 4);
        k_agg<D_HID / 4, true><<<(int)((work + T - 1) / T), T>>>(
            (const float4*)H1, b1, (float4*)OUT1, n);
    }

    // GEMM2: H2 = OUT1 @ W2
    {
        dim3 grid(D_OUT / 64, mblocks);
        k_gemm_tc<<<grid, 256, GEMM_SMEM>>>(OUT1, W2, H2, n, D_HID, D_OUT);
    }

    // aggregation layer 2: out = agg(H2) + b2
    {
        long long work = (long long)n * (D_OUT / 4);
        k_agg<D_OUT / 4, false><<<(int)((work + T - 1) / T), T>>>(
            (const float4*)H2, b2, (float4*)out, n);
    }
}